// round 10
// baseline (speedup 1.0000x reference)
#include <cuda_runtime.h>

#define BINS 64
#define BC 96                      // B*C = 32*3
#define PLANE 262144               // 512*512 per (b,c) plane
#define BPP 32                     // blocks per plane
#define CHUNK (PLANE / BPP)        // 8192 floats per block per tensor
#define THREADS 128
#define WARPS (THREADS / 32)       // 4
#define N4 (CHUNK / 4)             // 2048 float4 per block per tensor
#define GRID (BC * BPP)            // 3072 blocks

// Signed per-(plane,bin) count diff (+input, -target). Zero at module load;
// the last block restores it to zero each call -> graph-replay safe.
__device__ int g_diff[BC * BINS];
__device__ unsigned int g_count;

// bin = clip(floor((v+1)/step), 0, 63). Input domain [-1,1) => result >= 0.
// Exact-edge disagreement with searchsorted is ~1e-6 relative loss noise.
__device__ __forceinline__ int bin_of(float v) {
    return min(__float2int_rd(fmaf(v, 31.5f, 31.5f)), 63);
}

// s8 packing: 4 bins per 32-bit word. word(w,g,lane) = w*512 + g*32 + lane
// (g = bin>>2), byte = bin&3. word % 32 == lane for EVERY bin -> strictly
// conflict-free LDS/STS. Per-lane byte offset from its column base:
__device__ __forceinline__ int off_of(int b) {
    return ((b & ~3) << 5) | (b & 3);          // (bin>>2)*128 + (bin&3)
}

__global__ __launch_bounds__(THREADS)
void fused_kernel(const float4* __restrict__ inp, const float4* __restrict__ tgt,
                  float* __restrict__ out) {
    // TWO independent s8 sub-histograms per lane (A: x,z; B: y,w) -> two
    // overlapping RMW chains instead of one serialized chain. 2 sub x 4
    // warps x 2 KB = 16 KB. Range: <=32 values/tensor/thread/sub -> s8 ok.
    __shared__ signed char hist[2 * WARPS * 2048];   // 16 KB
    __shared__ unsigned int s_ticket;
    __shared__ float ssum[WARPS];

    const int tid  = threadIdx.x;
    const int lane = tid & 31;
    const int wid  = tid >> 5;

    int4* z4 = (int4*)hist;
    #pragma unroll
    for (int i = tid; i < (int)sizeof(hist) / 16; i += THREADS)
        z4[i] = make_int4(0, 0, 0, 0);
    __syncthreads();

    signed char* hA = &hist[wid * 2048 + lane * 4];  // lane-owned byte column
    signed char* hB = hA + WARPS * 2048;             // independent region

    const int plane = blockIdx.x / BPP;
    const int chunk = blockIdx.x % BPP;
    const size_t base4 = (size_t)plane * (PLANE / 4) + (size_t)chunk * N4;
    const float4* __restrict__ a = inp + base4;
    const float4* __restrict__ b = tgt + base4;

    #pragma unroll 4
    for (int i = tid; i < N4; i += THREADS) {
        float4 v = __ldcs(&a[i]);              // read-once: streaming
        float4 u = __ldcs(&b[i]);
        // Alternate A/B so consecutive RMWs are independent chains.
        hA[off_of(bin_of(v.x))] += 1;
        hB[off_of(bin_of(v.y))] += 1;
        hA[off_of(bin_of(v.z))] += 1;
        hB[off_of(bin_of(v.w))] += 1;
        hA[off_of(bin_of(u.x))] -= 1;
        hB[off_of(bin_of(u.y))] -= 1;
        hA[off_of(bin_of(u.z))] -= 1;
        hB[off_of(bin_of(u.w))] -= 1;
    }
    __syncthreads();

    // Fold: thread t -> bin = t&63, warp-pair half = t>>6. Extract byte
    // (bin&3) from each of 2 subs x 2 warps x 32 lanes words via masked
    // signed dp4a. Lane rotation (l+t)&31 -> bank (l+t)%32, conflict-free.
    {
        const int bin  = tid & 63;
        const int half = tid >> 6;
        const int g    = bin >> 2;
        const int mask = 1 << ((bin & 3) * 8);
        const int* W = (const int*)hist;
        int s = 0;
        #pragma unroll
        for (int sub = 0; sub < 2; sub++) {
            #pragma unroll
            for (int w = 0; w < 2; w++) {
                const int* row = W + sub * (WARPS * 512) + (2 * half + w) * 512 + g * 32;
                #pragma unroll
                for (int l = 0; l < 32; l++)
                    s = __dp4a(row[(l + tid) & 31], mask, s);
            }
        }
        if (s != 0) atomicAdd(&g_diff[plane * BINS + bin], s);
    }

    // Last block finishes the reduction (no separate kernel launch).
    __threadfence();
    if (tid == 0) s_ticket = atomicAdd(&g_count, 1u);
    __syncthreads();
    if (s_ticket == GRID - 1) {
        float s = 0.0f;
        for (int i = tid; i < BC * BINS; i += THREADS) {
            s += fabsf((float)__ldcg(&g_diff[i]));
            g_diff[i] = 0;                     // restore scratch for replay
        }
        #pragma unroll
        for (int o = 16; o > 0; o >>= 1)
            s += __shfl_down_sync(0xFFFFFFFFu, s, o);
        if (lane == 0) ssum[wid] = s;
        __syncthreads();
        if (tid == 0) {
            float t = ssum[0] + ssum[1] + ssum[2] + ssum[3];
            out[0] = t / ((float)PLANE * (float)(BC * BINS));
            g_count = 0u;                      // restore ticket for replay
        }
    }
}

extern "C" void kernel_launch(void* const* d_in, const int* in_sizes, int n_in,
                              void* d_out, int out_size) {
    const float* inp = (const float*)d_in[0];
    const float* tgt = (const float*)d_in[1];
    float* out = (float*)d_out;

    fused_kernel<<<GRID, THREADS>>>((const float4*)inp, (const float4*)tgt, out);
}

// round 11
// speedup vs baseline: 1.1188x; 1.1188x over previous
#include <cuda_runtime.h>

#define BINS 64
#define BC 96                      // B*C = 32*3
#define PLANE 262144               // 512*512 per (b,c) plane
#define BPP 32                     // blocks per plane
#define CHUNK (PLANE / BPP)        // 8192 floats per block per tensor
#define THREADS 128
#define WARPS (THREADS / 32)       // 4
#define N4 (CHUNK / 4)             // 2048 float4 per block per tensor
#define GRID (BC * BPP)            // 3072 blocks

// Signed per-(plane,bin) count diff (+input, -target). Zero at module load;
// the last block restores it to zero each call -> graph-replay safe.
__device__ int g_diff[BC * BINS];
__device__ unsigned int g_count;

// bin = clip(floor((v+1)/step), 0, 63). Input domain [-1,1) => result >= 0.
// Exact-edge disagreement with searchsorted is ~1e-6 relative loss noise.
__device__ __forceinline__ int bin_of(float v) {
    return min(__float2int_rd(fmaf(v, 31.5f, 31.5f)), 63);
}

// u16 packing, 2 bins/word: word(w,m,lane) = w*1024 + m*32 + lane (m=bin>>1),
// halfword = bin&1. word % 32 == lane for EVERY bin -> strictly
// conflict-free LDS/STS RMW. Halfword offset from the lane's column base:
__device__ __forceinline__ int slot_of(int b) {
    return ((b >> 1) << 6) | (b & 1);
}

__global__ __launch_bounds__(THREADS)
void fused_kernel(const float4* __restrict__ inp, const float4* __restrict__ tgt,
                  float* __restrict__ out) {
    __shared__ short hist[WARPS * BINS * 32];  // 16 KB
    __shared__ unsigned int s_ticket;
    __shared__ float ssum[WARPS];

    const int tid  = threadIdx.x;
    const int lane = tid & 31;
    const int wid  = tid >> 5;

    int4* z4 = (int4*)hist;
    #pragma unroll
    for (int i = tid; i < (int)sizeof(hist) / 16; i += THREADS)
        z4[i] = make_int4(0, 0, 0, 0);
    __syncthreads();

    // Lane-owned column: halfword index = wid*2048 + lane*2 + slot_of(bin).
    short* h = &hist[wid * 2048 + lane * 2];

    const int plane = blockIdx.x / BPP;
    const int chunk = blockIdx.x % BPP;
    const size_t base4 = (size_t)plane * (PLANE / 4) + (size_t)chunk * N4;
    const float4* __restrict__ a = inp + base4;
    const float4* __restrict__ b = tgt + base4;

    // Depth-1 software prefetch: issue iteration i+1's LDGs before the RMW
    // chain of iteration i, so DRAM latency overlaps the smem work.
    float4 va = __ldcs(&a[tid]);
    float4 vb = __ldcs(&b[tid]);
    for (int i = tid; i < N4; i += THREADS) {
        const int j = min(i + THREADS, N4 - 1);   // clamped (valid) prefetch
        float4 na = __ldcs(&a[j]);
        float4 nb = __ldcs(&b[j]);
        h[slot_of(bin_of(va.x))] += 1;
        h[slot_of(bin_of(va.y))] += 1;
        h[slot_of(bin_of(va.z))] += 1;
        h[slot_of(bin_of(va.w))] += 1;
        h[slot_of(bin_of(vb.x))] -= 1;
        h[slot_of(bin_of(vb.y))] -= 1;
        h[slot_of(bin_of(vb.z))] -= 1;
        h[slot_of(bin_of(vb.w))] -= 1;
        va = na;
        vb = nb;
    }
    __syncthreads();

    // Fold: thread t -> bin pair m = t>>2, warp w = t&3. Packed halfword
    // accumulation over 32 lanes (__vadd2: |sums| <= 8192, no overflow).
    // Rotation (k+t)&31 keeps banks distinct; shfl-combine the 4 warps.
    {
        const int m = tid >> 2;
        const int w = tid & 3;
        const int* words = (const int*)hist;
        int sp = 0;
        #pragma unroll
        for (int k = 0; k < 32; k++)
            sp = __vadd2(sp, words[w * 1024 + m * 32 + ((k + tid) & 31)]);
        sp = __vadd2(sp, __shfl_xor_sync(0xFFFFFFFFu, sp, 1));
        sp = __vadd2(sp, __shfl_xor_sync(0xFFFFFFFFu, sp, 2));
        if (w == 0) {
            int s_even = (int)(short)(sp & 0xFFFF);
            int s_odd  = sp >> 16;
            if (s_even) atomicAdd(&g_diff[plane * BINS + 2 * m], s_even);
            if (s_odd)  atomicAdd(&g_diff[plane * BINS + 2 * m + 1], s_odd);
        }
    }

    // Last block finishes the reduction (no separate kernel launch).
    __threadfence();
    if (tid == 0) s_ticket = atomicAdd(&g_count, 1u);
    __syncthreads();
    if (s_ticket == GRID - 1) {
        float s = 0.0f;
        for (int i = tid; i < BC * BINS; i += THREADS) {
            s += fabsf((float)__ldcg(&g_diff[i]));
            g_diff[i] = 0;                     // restore scratch for replay
        }
        #pragma unroll
        for (int o = 16; o > 0; o >>= 1)
            s += __shfl_down_sync(0xFFFFFFFFu, s, o);
        if (lane == 0) ssum[wid] = s;
        __syncthreads();
        if (tid == 0) {
            float t = ssum[0] + ssum[1] + ssum[2] + ssum[3];
            out[0] = t / ((float)PLANE * (float)(BC * BINS));
            g_count = 0u;                      // restore ticket for replay
        }
    }
}

extern "C" void kernel_launch(void* const* d_in, const int* in_sizes, int n_in,
                              void* d_out, int out_size) {
    const float* inp = (const float*)d_in[0];
    const float* tgt = (const float*)d_in[1];
    float* out = (float*)d_out;

    fused_kernel<<<GRID, THREADS>>>((const float4*)inp, (const float4*)tgt, out);
}